// round 17
// baseline (speedup 1.0000x reference)
#include <cuda_runtime.h>
#include <math.h>
#include <stdint.h>

#define DDIM    256
#define HWSZ    1024
#define NROWS   32768
#define KCODES  1024
#define QELEMS  8388608      // 32*256*32*32
#define TM      64
#define NTILE   64           // codes per B tile
#define NTILES  16
#define KC32    8            // 256 / 32 (fp8 K=32 per MMA)
#define NTHREADS 256
#define AP8     272          // bytes per fp8 A row (17*16: aligned, conflict-free)
#define BP8     272          // bytes per fp8 B row
#define XP      260          // fp32 Xs floats per row
#define BBYTES  (64 * BP8)   // 17408 per buffer

// ---- smem layout (bytes) ----
#define OFF_A8   0                       // 64 x AP8 fp8           17408
#define OFF_B    17408                   // 2 x (64 x BP8 fp8)     34816  (ends 52224)
// aliased over A8+B after GEMM:
#define OFF_XS   0                       // 64 x XP fp32           66560
#define OFF_SC   66560                   // sc[64][32] float        8192
#define OFF_CI   74752                   // ci[64][32] int          8192
#define OFF_WN   82944                   // wnorm[1024]             4096
#define OFF_XN   87040                   // xnorm[64]                256
#define OFF_PART 87296                   // reduce scratch[256]     1024
#define OFF_SW1  88320
#define OFF_SW2  88576
#define OFF_SI1  88832
#define OFF_SI2  89088
#define SMEM_BYTES 89344

#define DELTA 8.0f           // fp8-score refine threshold (~11 sigma)

__device__ float g_wnorm[KCODES];
__device__ float g_probs[KCODES];
__device__ float g_loss;
__device__ __align__(16) unsigned char g_W8[KCODES * DDIM];   // e4m3 copy of W

// ---------------------------------------------------------------------------
__device__ __forceinline__ void mma_e4m3(float* d, const uint32_t* a,
                                         uint32_t b0, uint32_t b1) {
    asm volatile(
        "mma.sync.aligned.m16n8k32.row.col.f32.e4m3.e4m3.f32 "
        "{%0,%1,%2,%3}, {%4,%5,%6,%7}, {%8,%9}, {%0,%1,%2,%3};"
        : "+f"(d[0]), "+f"(d[1]), "+f"(d[2]), "+f"(d[3])
        : "r"(a[0]), "r"(a[1]), "r"(a[2]), "r"(a[3]), "r"(b0), "r"(b1));
}
// pack 4 floats -> 4 e4m3 bytes, f0 in LSB
__device__ __forceinline__ uint32_t pack4_e4m3(float f0, float f1, float f2, float f3) {
    uint16_t lo, hi;
    asm("cvt.rn.satfinite.e4m3x2.f32 %0, %1, %2;" : "=h"(lo) : "f"(f1), "f"(f0));
    asm("cvt.rn.satfinite.e4m3x2.f32 %0, %1, %2;" : "=h"(hi) : "f"(f3), "f"(f2));
    return (uint32_t)lo | ((uint32_t)hi << 16);
}
__device__ __forceinline__ unsigned char cvt_e4m3(float v) {
    uint16_t h;
    asm("cvt.rn.satfinite.e4m3x2.f32 %0, %1, %2;" : "=h"(h) : "f"(0.0f), "f"(v));
    return (unsigned char)(h & 0xFF);
}
__device__ __forceinline__ uint32_t smem_u32(const void* p) {
    return (uint32_t)__cvta_generic_to_shared(p);
}

// ---------------------------------------------------------------------------
// Init: zero accumulators, wnorm per code, W -> e4m3 copy
// ---------------------------------------------------------------------------
__global__ void vq_init(const float* __restrict__ W) {
    int gt = blockIdx.x * 256 + threadIdx.x;
    if (gt < KCODES) g_probs[gt] = 0.0f;
    if (gt == 0) g_loss = 0.0f;
    int warp = threadIdx.x >> 5, lane = threadIdx.x & 31;
    int code = blockIdx.x * 8 + warp;
    const float4* wp = (const float4*)(W + (size_t)code * DDIM + lane * 8);
    float4 a = wp[0], b = wp[1];
    uint2 p;
    p.x = pack4_e4m3(a.x, a.y, a.z, a.w);
    p.y = pack4_e4m3(b.x, b.y, b.z, b.w);
    *(uint2*)(g_W8 + (size_t)code * DDIM + lane * 8) = p;
    float s = a.x*a.x + a.y*a.y + a.z*a.z + a.w*a.w
            + b.x*b.x + b.y*b.y + b.z*b.z + b.w*b.w;
    #pragma unroll
    for (int o = 16; o; o >>= 1) s += __shfl_xor_sync(0xffffffffu, s, o);
    if (lane == 0) g_wnorm[code] = s;
}

// ---------------------------------------------------------------------------
// Main fused kernel (TM=64, 2 CTAs/SM, fp8 m16n8k32, A frags in regs,
// cp.async double-buffered fp8 B)
// ---------------------------------------------------------------------------
__global__ void __launch_bounds__(NTHREADS, 2)
vq_main(const float* __restrict__ x, const float* __restrict__ W,
        float* __restrict__ out) {
    extern __shared__ __align__(1024) char smem[];
    const uint32_t sbase = smem_u32(smem);
    unsigned char* A8 = (unsigned char*)(smem + OFF_A8);
    float*  Xs   = (float*)(smem + OFF_XS);
    float*  sc   = (float*)(smem + OFF_SC);
    int*    ci   = (int*)  (smem + OFF_CI);
    float*  wn   = (float*)(smem + OFF_WN);
    float*  xn   = (float*)(smem + OFF_XN);
    float*  part = (float*)(smem + OFF_PART);
    float*  sw1  = (float*)(smem + OFF_SW1);
    float*  sw2  = (float*)(smem + OFF_SW2);
    int*    si1  = (int*)  (smem + OFF_SI1);
    int*    si2  = (int*)  (smem + OFF_SI2);

    const int t    = threadIdx.x;
    const int lane = t & 31;
    const int warp = t >> 5;
    const int g    = lane >> 2;
    const int tg   = lane & 3;
    const int wm   = warp & 3;           // M warp: rows wm*16 .. +15
    const int ng   = warp >> 2;          // N group (0..1)
    const int wnb  = ng * 32;

    const int row0 = blockIdx.x * TM;
    const int bb   = row0 / HWSZ;
    const int hw0  = row0 % HWSZ;
    const float* xblk = x + (size_t)bb * DDIM * HWSZ + hw0;   // elem (d,r): [d*HWSZ+r]
    float* enc = out + 2 + (size_t)QELEMS;

    // ---- prefetch B tile 0 (fp8, cp.async): 64 rows x 256 B = 1024 x 16B --
    {
        #pragma unroll
        for (int i = 0; i < 4; i++) {
            int idx = t + i * 256;
            int n = idx >> 4, c = idx & 15;
            uint32_t dst = sbase + OFF_B + (uint32_t)(n * BP8 + c * 16);
            const unsigned char* src = g_W8 + (size_t)n * DDIM + c * 16;
            asm volatile("cp.async.cg.shared.global [%0], [%1], 16;" :: "r"(dst), "l"(src));
        }
        asm volatile("cp.async.commit_group;" ::: "memory");
    }

    // stage wnorm
    for (int i = t; i < KCODES; i += NTHREADS) wn[i] = g_wnorm[i];

    // zero this CTA's encodings rows (enc base only 8B-aligned: float2)
    {
        float2 z = make_float2(0.f, 0.f);
        float2* e2 = (float2*)(enc + (size_t)row0 * KCODES);
        #pragma unroll 8
        for (int i = 0; i < 128; i++) e2[t + i * 256] = z;
    }

    // load x -> e4m3 A smem [r][d] (pitch 272B), accumulate xnorm partials
    {
        int r = t & 63;
        float acc = 0.0f;
        #pragma unroll 4
        for (int i = 0; i < 64; i++) {
            int d = (t >> 6) + i * 4;
            float v = __ldg(xblk + (size_t)d * HWSZ + r);
            acc = fmaf(v, v, acc);
            A8[r * AP8 + d] = cvt_e4m3(v);
        }
        part[t] = acc;
    }
    __syncthreads();
    if (t < TM) xn[t] = part[t] + part[t + 64] + part[t + 128] + part[t + 192];

    // ---- preload A fragments into registers: 8 chunks x 4 regs -----------
    uint32_t afr[KC32][4];
    {
        const uint32_t abase = sbase + OFF_A8 +
            (uint32_t)((wm * 16 + g) * AP8 + 4 * tg);
        #pragma unroll
        for (int kc = 0; kc < KC32; kc++) {
            uint32_t a0, a1, a2, a3;
            asm volatile("ld.shared.b32 %0, [%1];" : "=r"(a0) : "r"(abase + kc * 32));
            asm volatile("ld.shared.b32 %0, [%1];" : "=r"(a1) : "r"(abase + kc * 32 + 8 * AP8));
            asm volatile("ld.shared.b32 %0, [%1];" : "=r"(a2) : "r"(abase + kc * 32 + 16));
            asm volatile("ld.shared.b32 %0, [%1];" : "=r"(a3) : "r"(abase + kc * 32 + 8 * AP8 + 16));
            afr[kc][0] = a0; afr[kc][1] = a1; afr[kc][2] = a2; afr[kc][3] = a3;
        }
    }

    // B fragment lane base addresses (per ni): row = wnb+ni*8+g, byte 4tg
    uint32_t b_lane[4];
    #pragma unroll
    for (int ni = 0; ni < 4; ni++)
        b_lane[ni] = sbase + OFF_B + (uint32_t)((wnb + ni * 8 + g) * BP8 + 4 * tg);

    // ---- pipelined GEMM over 16 column tiles + per-owner top-4 ----------
    float ts[2][4]; int ti[2][4];
    #pragma unroll
    for (int s = 0; s < 2; s++)
        #pragma unroll
        for (int q = 0; q < 4; q++) { ts[s][q] = 3.4e38f; ti[s][q] = 0; }

    for (int nt = 0; nt < NTILES; nt++) {
        if (nt + 1 < NTILES) {
            const int n0n = (nt + 1) * NTILE;
            const uint32_t bo = (uint32_t)(((nt + 1) & 1) * BBYTES);
            #pragma unroll
            for (int i = 0; i < 4; i++) {
                int idx = t + i * 256;
                int n = idx >> 4, c = idx & 15;
                uint32_t dst = sbase + OFF_B + bo + (uint32_t)(n * BP8 + c * 16);
                const unsigned char* src = g_W8 + (size_t)(n0n + n) * DDIM + c * 16;
                asm volatile("cp.async.cg.shared.global [%0], [%1], 16;" :: "r"(dst), "l"(src));
            }
            asm volatile("cp.async.commit_group;" ::: "memory");
            asm volatile("cp.async.wait_group 1;" ::: "memory");
        } else {
            asm volatile("cp.async.wait_group 0;" ::: "memory");
        }
        __syncthreads();

        const uint32_t bufo = (uint32_t)((nt & 1) * BBYTES);
        float acc[4][4];
        #pragma unroll
        for (int ni = 0; ni < 4; ni++)
            #pragma unroll
            for (int q = 0; q < 4; q++) acc[ni][q] = 0.0f;

        #pragma unroll
        for (int kc = 0; kc < KC32; kc++) {
            #pragma unroll
            for (int ni = 0; ni < 4; ni++) {
                uint32_t b0, b1;
                asm volatile("ld.shared.b32 %0, [%1];" : "=r"(b0) : "r"(b_lane[ni] + bufo + kc * 32));
                asm volatile("ld.shared.b32 %0, [%1];" : "=r"(b1) : "r"(b_lane[ni] + bufo + kc * 32 + 16));
                mma_e4m3(acc[ni], afr[kc], b0, b1);
            }
        }

        // fold scores into per-half top-4
        const int n0 = nt * NTILE;
        #pragma unroll
        for (int half = 0; half < 2; half++) {
            #pragma unroll
            for (int ni = 0; ni < 4; ni++) {
                #pragma unroll
                for (int j = 0; j < 2; j++) {
                    const int c = n0 + wnb + ni * 8 + 2 * tg + j;
                    float v = wn[c] - 2.0f * acc[ni][half * 2 + j];
                    if (v < ts[half][3]) {
                        ts[half][3] = v; ti[half][3] = c;
                        #pragma unroll
                        for (int q = 3; q > 0; --q) {
                            if (ts[half][q] < ts[half][q-1]) {
                                float f = ts[half][q]; ts[half][q] = ts[half][q-1]; ts[half][q-1] = f;
                                int  ii = ti[half][q]; ti[half][q] = ti[half][q-1]; ti[half][q-1] = ii;
                            }
                        }
                    }
                }
            }
        }
        __syncthreads();   // all B reads done before buffer rewrite
    }

    // ---- restage x fp32 into Xs (aliases A8+B; all GEMM reads done) ------
    {
        int r = t & 63;
        #pragma unroll 4
        for (int i = 0; i < 64; i++) {
            int d = (t >> 6) + i * 4;
            Xs[r * XP + d] = __ldg(xblk + (size_t)d * HWSZ + r);
        }
    }
    // write candidates (separate region)
    {
        const int o = ng * 4 + tg;   // owner 0..7
        #pragma unroll
        for (int half = 0; half < 2; half++) {
            const int r = wm * 16 + half * 8 + g;
            #pragma unroll
            for (int q = 0; q < 4; q++) {
                sc[r * 32 + o * 4 + q] = ts[half][q];
                ci[r * 32 + o * 4 + q] = ti[half][q];
            }
        }
    }
    __syncthreads();

    // ---- thresholded exact fp32 refine (thread-per-row) ------------------
    if (t < TM) {
        const int r = t;
        const float xnr = xn[r];
        float m1 = 3.4e38f, m2 = 3.4e38f;
        #pragma unroll 8
        for (int q = 0; q < 32; q++) {
            float s = sc[r * 32 + q];
            if (s < m1) { m2 = m1; m1 = s; } else if (s < m2) m2 = s;
        }
        const float thr = m2 + DELTA;
        float b1 = 3.4e38f, b2 = 3.4e38f; int j1 = 0, j2 = 0;
        for (int q = 0; q < 32; q++) {
            if (sc[r * 32 + q] > thr) continue;
            const int c = ci[r * 32 + q];
            const float4* wp = (const float4*)(W + (size_t)c * DDIM);
            const float4* ap = (const float4*)(Xs + r * XP);
            float p = 0.0f;
            #pragma unroll 8
            for (int i = 0; i < 64; i++) {
                float4 wv = __ldg(wp + i);
                float4 av = ap[i];
                p = fmaf(av.x, wv.x, p); p = fmaf(av.y, wv.y, p);
                p = fmaf(av.z, wv.z, p); p = fmaf(av.w, wv.w, p);
            }
            float dist = xnr + wn[c] - 2.0f * p;
            if (dist < b1)      { b2 = b1; j2 = j1; b1 = dist; j1 = c; }
            else if (dist < b2) { b2 = dist; j2 = c; }
        }
        float inv1 = 1.0f / b1, inv2 = 1.0f / b2;
        float nrm = fmaxf(sqrtf(fmaf(inv1, inv1, inv2 * inv2)), 1e-12f);
        float w1o = inv1 / nrm, w2o = inv2 / nrm;
        sw1[r] = w1o; sw2[r] = w2o; si1[r] = j1; si2[r] = j2;
        size_t grow = (size_t)(row0 + r);
        enc[grow * KCODES + j1] = w1o;
        enc[grow * KCODES + j2] = w2o;
        atomicAdd(&g_probs[j1], w1o);
        atomicAdd(&g_probs[j2], w2o);
    }
    __syncthreads();

    // ---- quantized rows (NCHW) + loss partial ----------------------------
    {
        const int r  = t & 63;
        const int d0 = (t >> 6) * 64;
        const float w1o = sw1[r], w2o = sw2[r];
        const float* wr1 = W + (size_t)si1[r] * DDIM;
        const float* wr2 = W + (size_t)si2[r] * DDIM;
        float* qo = out + 1 + (size_t)bb * DDIM * HWSZ + hw0 + r;
        float lacc = 0.0f;
        for (int d = d0; d < d0 + 64; d += 4) {
            float4 wa = __ldg((const float4*)(wr1 + d));
            float4 wb = __ldg((const float4*)(wr2 + d));
            float4 av = *(const float4*)(Xs + r * XP + d);
            float q0 = fmaf(w1o, wa.x, w2o * wb.x);
            float q1 = fmaf(w1o, wa.y, w2o * wb.y);
            float q2 = fmaf(w1o, wa.z, w2o * wb.z);
            float q3 = fmaf(w1o, wa.w, w2o * wb.w);
            float e;
            e = q0 - av.x; lacc = fmaf(e, e, lacc); qo[(size_t)(d + 0) * HWSZ] = q0;
            e = q1 - av.y; lacc = fmaf(e, e, lacc); qo[(size_t)(d + 1) * HWSZ] = q1;
            e = q2 - av.z; lacc = fmaf(e, e, lacc); qo[(size_t)(d + 2) * HWSZ] = q2;
            e = q3 - av.w; lacc = fmaf(e, e, lacc); qo[(size_t)(d + 3) * HWSZ] = q3;
        }
        #pragma unroll
        for (int o = 16; o; o >>= 1) lacc += __shfl_xor_sync(0xffffffffu, lacc, o);
        __syncthreads();
        if ((t & 31) == 0) part[t >> 5] = lacc;
        __syncthreads();
        if (t == 0) {
            float s = 0.0f;
            #pragma unroll
            for (int w = 0; w < 8; w++) s += part[w];
            atomicAdd(&g_loss, s);
        }
    }
}

// ---------------------------------------------------------------------------
// Finalize: perplexity + loss scalars
// ---------------------------------------------------------------------------
__global__ void vq_final(float* __restrict__ out) {
    __shared__ float red[32];
    int t = threadIdx.x;                 // 1024 threads
    float p = g_probs[t] * (1.0f / 32768.0f);
    float e = -p * logf(p + 1e-10f);
    #pragma unroll
    for (int o = 16; o; o >>= 1) e += __shfl_xor_sync(0xffffffffu, e, o);
    if ((t & 31) == 0) red[t >> 5] = e;
    __syncthreads();
    if (t == 0) {
        float s = 0.0f;
        #pragma unroll
        for (int w = 0; w < 32; w++) s += red[w];
        out[(size_t)QELEMS + 1] = expf(s);              // perplexity
        out[0] = 1.25f * g_loss / (float)QELEMS;        // loss
    }
}

// ---------------------------------------------------------------------------
extern "C" void kernel_launch(void* const* d_in, const int* in_sizes, int n_in,
                              void* d_out, int out_size) {
    const float* x = (const float*)d_in[0];   // (32,256,32,32) fp32
    const float* W = (const float*)d_in[1];   // (1024,256) fp32
    float* out = (float*)d_out;
    (void)in_sizes; (void)n_in; (void)out_size;

    cudaFuncSetAttribute(vq_main, cudaFuncAttributeMaxDynamicSharedMemorySize, SMEM_BYTES);
    vq_init<<<128, 256>>>(W);
    vq_main<<<NROWS / TM, NTHREADS, SMEM_BYTES>>>(x, W, out);
    vq_final<<<1, 1024>>>(out);
}